// round 4
// baseline (speedup 1.0000x reference)
#include <cuda_runtime.h>
#include <math.h>

#define BB   256      // batch
#define TT   512      // time steps
#define IDIM 128      // input dim
#define HH   256      // hidden dim
#define CDIM 1000     // classes
#define G4   (4*HH)   // 1024 gate columns
#define NCTA 128      // persistent grid size (8 x 16)

// ---------------- scratch (static device allocations; no cudaMalloc) ----------------
__device__ float g_xp[(size_t)BB * TT * G4];   // input projection for current layer
__device__ float g_hs[(size_t)BB * TT * HH];   // layer-0 hidden sequence
__device__ float g_h[2][BB * HH];              // double-buffered hidden state
__device__ unsigned int          g_arrive;     // cumulative barrier arrivals
__device__ volatile unsigned int g_release;    // barrier release counter

// ---------------- helpers ----------------
__device__ __forceinline__ float sigmoidf_(float x) {
    return 1.0f / (1.0f + __expf(-x));
}
__device__ __forceinline__ float tanhf_(float x) {
    float ax = fabsf(x);
    float e  = __expf(-2.0f * ax);
    float r  = (1.0f - e) / (1.0f + e);
    return copysignf(r, x);
}

// packed f32x2 (Blackwell): d = a*b + d over 2 lanes
__device__ __forceinline__ void fma2_(unsigned long long& d,
                                      unsigned long long a,
                                      unsigned long long b) {
    asm("fma.rn.f32x2 %0, %1, %2, %3;" : "=l"(d) : "l"(a), "l"(b), "l"(d));
}
__device__ __forceinline__ unsigned long long bcast2_(float x) {
    unsigned long long r;
    asm("mov.b64 %0, {%1, %1};" : "=l"(r) : "f"(x));
    return r;
}
__device__ __forceinline__ float2 unpack2_(unsigned long long v) {
    float2 r;
    asm("mov.b64 {%0, %1}, %2;" : "=f"(r.x), "=f"(r.y) : "l"(v));
    return r;
}

// ---------------- input projection: g_xp[m,n] = A[m,:] . W[n,:] + b1[n] + b2[n] ----------------
// A: [M, K] row-major (M = B*T), W: [4H, K] row-major, output [M, 4H].
// BM=128, BN=128, BK=16; 256 threads; 8x8 micro-tile per thread via fma.rn.f32x2.
#define PBM 128
#define PBN 128
#define PBK 16

__global__ __launch_bounds__(256, 2) void proj_kernel(
    const float* __restrict__ A_ext, int use_hs,
    const float* __restrict__ W,
    const float* __restrict__ b1, const float* __restrict__ b2,
    int K)
{
    __shared__ float As[PBK][PBM];
    __shared__ float Bs[PBK][PBN];

    const float* A = use_hs ? g_hs : A_ext;
    const int N   = G4;
    const int tid = threadIdx.x;
    const int m0  = blockIdx.y * PBM;
    const int n0  = blockIdx.x * PBN;
    const int tx  = tid & 15;   // 16 groups over N (8 cols each)
    const int ty  = tid >> 4;   // 16 groups over M (8 rows each)

    unsigned long long acc[8][4];
#pragma unroll
    for (int i = 0; i < 8; i++)
#pragma unroll
        for (int j = 0; j < 4; j++) acc[i][j] = 0ull;

    for (int kk = 0; kk < K; kk += PBK) {
        // load A tile: 128x16 = 512 float4, 2 per thread
#pragma unroll
        for (int it = 0; it < 2; it++) {
            int id  = tid + it * 256;
            int row = id >> 2;
            int kq  = id & 3;
            float4 v = *(const float4*)(A + (size_t)(m0 + row) * K + kk + kq * 4);
            As[kq * 4 + 0][row] = v.x;
            As[kq * 4 + 1][row] = v.y;
            As[kq * 4 + 2][row] = v.z;
            As[kq * 4 + 3][row] = v.w;
        }
        // load W tile: 128x16 = 512 float4, 2 per thread
#pragma unroll
        for (int it = 0; it < 2; it++) {
            int id  = tid + it * 256;
            int row = id >> 2;
            int kq  = id & 3;
            float4 v = *(const float4*)(W + (size_t)(n0 + row) * K + kk + kq * 4);
            Bs[kq * 4 + 0][row] = v.x;
            Bs[kq * 4 + 1][row] = v.y;
            Bs[kq * 4 + 2][row] = v.z;
            Bs[kq * 4 + 3][row] = v.w;
        }
        __syncthreads();

#pragma unroll
        for (int k = 0; k < PBK; k++) {
            float4 a0 = *(const float4*)&As[k][ty * 8];
            float4 a1 = *(const float4*)&As[k][ty * 8 + 4];
            const ulonglong2* bp = (const ulonglong2*)&Bs[k][tx * 8];
            ulonglong2 bA = bp[0];   // n-pairs (0,1) and (2,3)
            ulonglong2 bB = bp[1];   // n-pairs (4,5) and (6,7)
            unsigned long long am[8];
            am[0] = bcast2_(a0.x); am[1] = bcast2_(a0.y);
            am[2] = bcast2_(a0.z); am[3] = bcast2_(a0.w);
            am[4] = bcast2_(a1.x); am[5] = bcast2_(a1.y);
            am[6] = bcast2_(a1.z); am[7] = bcast2_(a1.w);
#pragma unroll
            for (int i = 0; i < 8; i++) {
                fma2_(acc[i][0], am[i], bA.x);
                fma2_(acc[i][1], am[i], bA.y);
                fma2_(acc[i][2], am[i], bB.x);
                fma2_(acc[i][3], am[i], bB.y);
            }
        }
        __syncthreads();
    }

    float bias[8];
#pragma unroll
    for (int j = 0; j < 8; j++) {
        int n = n0 + tx * 8 + j;
        bias[j] = b1[n] + b2[n];
    }
#pragma unroll
    for (int i = 0; i < 8; i++) {
        float* op = g_xp + (size_t)(m0 + ty * 8 + i) * N + n0 + tx * 8;
        float4 o0, o1;
        float2 p;
        p = unpack2_(acc[i][0]); o0.x = p.x + bias[0]; o0.y = p.y + bias[1];
        p = unpack2_(acc[i][1]); o0.z = p.x + bias[2]; o0.w = p.y + bias[3];
        p = unpack2_(acc[i][2]); o1.x = p.x + bias[4]; o1.y = p.y + bias[5];
        p = unpack2_(acc[i][3]); o1.z = p.x + bias[6]; o1.w = p.y + bias[7];
        *(float4*)(op)     = o0;
        *(float4*)(op + 4) = o1;
    }
}

// ---------------- persistent LSTM layer kernel ----------------
// Grid (8, 16): blockIdx.x = batch slice of 32, blockIdx.y = hidden-col slice of 16.
// 256 threads: tid = bl*8 + jg;  bl in [0,32) local batch, jg in [0,8) j-pair.
// Each thread owns (1 batch) x (2 hidden cols) x (all 4 gates); c-state in registers.
// Whh slice (4 gates x 16 j x 256 k) stays in SMEM for all 512 steps.
#define W2F_FLOATS (4 * 8 * 258 * 2)           // 16512
#define HS_FLOATS  (32 * 260)                  // 8320
#define PERSIST_SMEM_BYTES ((W2F_FLOATS + HS_FLOATS) * 4)

__global__ __launch_bounds__(256, 1) void lstm_persist_kernel(
    const float* __restrict__ Whh, int write_hs)
{
    extern __shared__ float smem[];
    float* w2f = smem;
    float* h_s = smem + W2F_FLOATS;

    const int tid = threadIdx.x;
    const int jg  = tid & 7;
    const int bl  = tid >> 3;
    const int b0  = blockIdx.x * 32;
    const int j0  = blockIdx.y * 16;
    const int b   = b0 + bl;
    const int j   = j0 + 2 * jg;

    // ---- load Whh slice into SMEM as j-pairs
    for (int idx = tid; idx < 4096; idx += 256) {
        int row = idx >> 6;          // 0..63 local gate-row
        int kq  = idx & 63;          // k quad
        int g   = row >> 4;
        int jj  = row & 15;
        float4 v = *(const float4*)(Whh + (size_t)(g * HH + j0 + jj) * HH + kq * 4);
        int jp   = jj >> 1;
        int lane = jj & 1;
        float* dst = w2f + ((g * 8 + jp) * 258 + kq * 4) * 2 + lane;
        dst[0] = v.x; dst[2] = v.y; dst[4] = v.z; dst[6] = v.w;
    }
    __syncthreads();

    float c0 = 0.0f, c1 = 0.0f;

    for (int t = 0; t < TT; t++) {
        const float* __restrict__ hprev = g_h[t & 1];
        float* __restrict__ hnext       = g_h[(t & 1) ^ 1];

        unsigned long long accA[4], accB[4];
#pragma unroll
        for (int g = 0; g < 4; g++) { accA[g] = 0ull; accB[g] = 0ull; }

        if (t > 0) {
            // stage h slice (must bypass L1: written by other SMs last step)
            for (int i = tid; i < 2048; i += 256) {
                int row = i >> 6;
                int kq  = i & 63;
                float4 v = __ldcg((const float4*)(hprev + (size_t)(b0 + row) * HH + kq * 4));
                *(float4*)&h_s[row * 260 + kq * 4] = v;
            }
            __syncthreads();

#pragma unroll 4
            for (int k = 0; k < HH; k += 4) {
                float4 hv = *(const float4*)&h_s[bl * 260 + k];
                unsigned long long h2a = bcast2_(hv.x);
                unsigned long long h2b = bcast2_(hv.y);
                unsigned long long h2c = bcast2_(hv.z);
                unsigned long long h2d = bcast2_(hv.w);
#pragma unroll
                for (int g = 0; g < 4; g++) {
                    const ulonglong2* wp =
                        (const ulonglong2*)(w2f + ((g * 8 + jg) * 258 + k) * 2);
                    ulonglong2 wA = wp[0];   // pairs at k, k+1
                    ulonglong2 wB = wp[1];   // pairs at k+2, k+3
                    fma2_(accA[g], h2a, wA.x);
                    fma2_(accB[g], h2b, wA.y);
                    fma2_(accA[g], h2c, wB.x);
                    fma2_(accB[g], h2d, wB.y);
                }
            }
        }

        // ---- gates = acc + xp ; elementwise update (c in registers)
        float2 gate[4];
#pragma unroll
        for (int g = 0; g < 4; g++) {
            float2 a  = unpack2_(accA[g]);
            float2 bb = unpack2_(accB[g]);
            float2 xv = *(const float2*)(g_xp + ((size_t)b * TT + t) * G4 + g * HH + j);
            gate[g].x = a.x + bb.x + xv.x;
            gate[g].y = a.y + bb.y + xv.y;
        }
        float i0 = sigmoidf_(gate[0].x), i1 = sigmoidf_(gate[0].y);
        float f0 = sigmoidf_(gate[1].x), f1 = sigmoidf_(gate[1].y);
        float g0 = tanhf_   (gate[2].x), g1 = tanhf_   (gate[2].y);
        float o0 = sigmoidf_(gate[3].x), o1 = sigmoidf_(gate[3].y);
        c0 = f0 * c0 + i0 * g0;
        c1 = f1 * c1 + i1 * g1;
        float2 hv2;
        hv2.x = o0 * tanhf_(c0);
        hv2.y = o1 * tanhf_(c1);
        __stcg((float2*)(hnext + (size_t)b * HH + j), hv2);
        if (write_hs)
            *(float2*)(g_hs + ((size_t)b * TT + t) * HH + j) = hv2;

        // ---- grid barrier (cumulative counter; survives replays/launches)
        __syncthreads();
        if (tid == 0) {
            __threadfence();
            unsigned cnt    = atomicAdd(&g_arrive, 1u) + 1u;
            unsigned target = ((cnt + NCTA - 1u) / NCTA) * NCTA;
            if (cnt == target) {
                g_release = cnt;
            } else {
                while ((int)(g_release - target) < 0) __nanosleep(32);
            }
            __threadfence();
        }
        __syncthreads();
    }
}

// ---------------- final classifier ----------------
__global__ __launch_bounds__(256) void fc_kernel(
    const float* __restrict__ fcW, const float* __restrict__ fcb,
    float* __restrict__ out)
{
    __shared__ float hrow[HH];
    const int b = blockIdx.x;
    const float* __restrict__ h = g_h[0];   // final h after 512 steps lands in buffer 0
    for (int k = threadIdx.x; k < HH; k += 256) hrow[k] = h[b * HH + k];
    __syncthreads();

    for (int c = threadIdx.x; c < CDIM; c += 256) {
        const float* __restrict__ w = fcW + (size_t)c * HH;
        float s = fcb[c];
#pragma unroll
        for (int k = 0; k < HH; k += 4) {
            float4 wv = *(const float4*)(w + k);
            s += hrow[k + 0] * wv.x;
            s += hrow[k + 1] * wv.y;
            s += hrow[k + 2] * wv.z;
            s += hrow[k + 3] * wv.w;
        }
        out[(size_t)b * CDIM + c] = s;
    }
}

// ---------------- launch ----------------
extern "C" void kernel_launch(void* const* d_in, const int* in_sizes, int n_in,
                              void* d_out, int out_size)
{
    const float* x    = (const float*)d_in[0];
    const float* Wih0 = (const float*)d_in[1];
    const float* Whh0 = (const float*)d_in[2];
    const float* bih0 = (const float*)d_in[3];
    const float* bhh0 = (const float*)d_in[4];
    const float* Wih1 = (const float*)d_in[5];
    const float* Whh1 = (const float*)d_in[6];
    const float* bih1 = (const float*)d_in[7];
    const float* bhh1 = (const float*)d_in[8];
    const float* fcW  = (const float*)d_in[9];
    const float* fcb  = (const float*)d_in[10];
    float* out = (float*)d_out;

    cudaFuncSetAttribute(lstm_persist_kernel,
                         cudaFuncAttributeMaxDynamicSharedMemorySize,
                         PERSIST_SMEM_BYTES);

    const dim3 proj_grid(G4 / PBN, (BB * TT) / PBM);  // (8, 1024)
    const dim3 pers_grid(BB / 32, HH / 16);           // (8, 16) = 128 CTAs

    // ---- layer 0 ----
    proj_kernel<<<proj_grid, 256>>>(x, 0, Wih0, bih0, bhh0, IDIM);
    lstm_persist_kernel<<<pers_grid, 256, PERSIST_SMEM_BYTES>>>(Whh0, 1);

    // ---- layer 1 ----
    proj_kernel<<<proj_grid, 256>>>(nullptr, 1, Wih1, bih1, bhh1, HH);
    lstm_persist_kernel<<<pers_grid, 256, PERSIST_SMEM_BYTES>>>(Whh1, 0);

    // ---- classifier ----
    fc_kernel<<<BB, 256>>>(fcW, fcb, out);
}

// round 6
// speedup vs baseline: 1.0870x; 1.0870x over previous
#include <cuda_runtime.h>
#include <cuda_bf16.h>
#include <math.h>
#include <cstdint>

#define BB   256      // batch
#define TT   512      // time steps
#define IDIM 128      // input dim
#define HH   256      // hidden dim
#define CDIM 1000     // classes
#define G4   (4*HH)   // 1024 gate columns
#define NCTA 128      // persistent grid size (8 x 16)

// ---------------- scratch (static device allocations; no cudaMalloc) ----------------
__device__ float g_xp[(size_t)BB * TT * G4];   // input projection for current layer
__device__ float g_hs[(size_t)BB * TT * HH];   // layer-0 hidden sequence
__device__ float g_h[2][BB * HH];              // double-buffered hidden state
__device__ unsigned int          g_arrive;     // cumulative barrier arrivals
__device__ volatile unsigned int g_release;    // barrier release counter

// bf16 split buffers for tensor-core projections
__device__ __nv_bfloat16 g_a_hi[(size_t)BB * TT * HH];
__device__ __nv_bfloat16 g_a_lo[(size_t)BB * TT * HH];
__device__ __nv_bfloat16 g_w_hi[(size_t)G4 * HH];
__device__ __nv_bfloat16 g_w_lo[(size_t)G4 * HH];

// ---------------- generic helpers ----------------
__device__ __forceinline__ float sigmoidf_(float x) {
    return 1.0f / (1.0f + __expf(-x));
}
__device__ __forceinline__ float tanhf_(float x) {
    float ax = fabsf(x);
    float e  = __expf(-2.0f * ax);
    float r  = (1.0f - e) / (1.0f + e);
    return copysignf(r, x);
}
__device__ __forceinline__ void fma2_(unsigned long long& d,
                                      unsigned long long a,
                                      unsigned long long b) {
    asm("fma.rn.f32x2 %0, %1, %2, %3;" : "=l"(d) : "l"(a), "l"(b), "l"(d));
}
__device__ __forceinline__ unsigned long long bcast2_(float x) {
    unsigned long long r;
    asm("mov.b64 %0, {%1, %1};" : "=l"(r) : "f"(x));
    return r;
}
__device__ __forceinline__ float2 unpack2_(unsigned long long v) {
    float2 r;
    asm("mov.b64 {%0, %1}, %2;" : "=f"(r.x), "=f"(r.y) : "l"(v));
    return r;
}
__device__ __forceinline__ uint32_t smem_u32_(const void* p) {
    uint32_t a;
    asm("{ .reg .u64 t; cvta.to.shared.u64 t, %1; cvt.u32.u64 %0, t; }"
        : "=r"(a) : "l"(p));
    return a;
}
static __device__ __forceinline__ uint32_t sw128(uint32_t off) {
    return off ^ ((off >> 3) & 0x70);
}

// cp.async (sm_80+; base-target safe)
__device__ __forceinline__ void cp16_(void* smem_dst, const void* gsrc) {
    uint32_t d = smem_u32_(smem_dst);
    asm volatile("cp.async.cg.shared.global [%0], [%1], 16;" :: "r"(d), "l"(gsrc));
}
#define CP_COMMIT() asm volatile("cp.async.commit_group;" ::: "memory")
#define CP_WAIT1()  asm volatile("cp.async.wait_group 1;" ::: "memory")
#define CP_WAIT0()  asm volatile("cp.async.wait_group 0;" ::: "memory")

// ldmatrix x4 (sm_75+)
#define LDMATRIX_X4(r0, r1, r2, r3, addr) \
    asm volatile("ldmatrix.sync.aligned.m8n8.x4.shared.b16 {%0,%1,%2,%3}, [%4];" \
                 : "=r"(r0), "=r"(r1), "=r"(r2), "=r"(r3) : "r"(addr))

// mma m16n8k16 bf16 (sm_80+)
#define MMA_BF16(d, a, b0v, b1v) \
    asm volatile("mma.sync.aligned.m16n8k16.row.col.f32.bf16.bf16.f32 " \
                 "{%0,%1,%2,%3}, {%4,%5,%6,%7}, {%8,%9}, {%0,%1,%2,%3};" \
                 : "+f"((d)[0]), "+f"((d)[1]), "+f"((d)[2]), "+f"((d)[3]) \
                 : "r"((a)[0]), "r"((a)[1]), "r"((a)[2]), "r"((a)[3]), \
                   "r"(b0v), "r"(b1v))

// ---------------- bf16 split conversion ----------------
__global__ __launch_bounds__(256) void split_bf16_kernel(
    const float* __restrict__ src_ext, int use_hs, int to_w, size_t n4)
{
    size_t i = (size_t)blockIdx.x * blockDim.x + threadIdx.x;
    if (i >= n4) return;
    const float4* s = (const float4*)(use_hs ? (const float*)g_hs : src_ext);
    __nv_bfloat162* dh = (__nv_bfloat162*)(to_w ? g_w_hi : g_a_hi);
    __nv_bfloat162* dl = (__nv_bfloat162*)(to_w ? g_w_lo : g_a_lo);
    float4 v = s[i];
    __nv_bfloat16 h0 = __float2bfloat16(v.x);
    __nv_bfloat16 h1 = __float2bfloat16(v.y);
    __nv_bfloat16 h2 = __float2bfloat16(v.z);
    __nv_bfloat16 h3 = __float2bfloat16(v.w);
    __nv_bfloat16 l0 = __float2bfloat16(v.x - __bfloat162float(h0));
    __nv_bfloat16 l1 = __float2bfloat16(v.y - __bfloat162float(h1));
    __nv_bfloat16 l2 = __float2bfloat16(v.z - __bfloat162float(h2));
    __nv_bfloat16 l3 = __float2bfloat16(v.w - __bfloat162float(h3));
    dh[i * 2 + 0] = __halves2bfloat162(h0, h1);
    dh[i * 2 + 1] = __halves2bfloat162(h2, h3);
    dl[i * 2 + 0] = __halves2bfloat162(l0, l1);
    dl[i * 2 + 1] = __halves2bfloat162(l2, l3);
}

// ---------------- HMMA projection ----------------
// Output tile: 128(M) x 128(N). 256 threads = 8 warps, 4(m) x 2(n); warp tile 32x64.
// K pipeline: 3 splits (hi*hi, w_lo, a_lo) x (K/64) chunks; BK=64 bf16 (128B rows,
// SW128 swizzled SMEM, ldmatrix-friendly). 2-stage cp.async pipeline.
#define PSTG 16384                          // one 128x64 bf16 tile
#define PROJ_SMEM_TOTAL (4 * PSTG + 512)    // 2 stages x (A,B) + bias

__global__ __launch_bounds__(256) void proj_mma_kernel(
    const float* __restrict__ b1, const float* __restrict__ b2, int K)
{
    extern __shared__ char smem[];
    float* bias_s = (float*)(smem + 4 * PSTG);

    const int tid  = threadIdx.x;
    const int lane = tid & 31;
    const int w    = tid >> 5;
    const int wm   = w & 3;        // 4 m-slices of 32 rows
    const int wn   = w >> 2;       // 2 n-slices of 64 cols
    const int n0   = blockIdx.x * 128;
    const int m0   = blockIdx.y * 128;

    if (tid < 128) bias_s[tid] = b1[n0 + tid] + b2[n0 + tid];

    const int kchunks = K >> 6;
    const int C = 3 * kchunks;

    // prefetch helper (inlined twice below)
    auto prefetch = [&](int c, int stage) {
        const int s  = c / kchunks;
        const int kc = c % kchunks;
        const __nv_bfloat16* a_src = (s == 2) ? g_a_lo : g_a_hi;
        const __nv_bfloat16* w_src = (s == 1) ? g_w_lo : g_w_hi;
        char* abuf = smem + stage * 2 * PSTG;
        char* bbuf = abuf + PSTG;
#pragma unroll
        for (int i = 0; i < 4; i++) {
            int id  = tid + i * 256;          // 0..1023
            int row = id >> 3;
            int ch  = id & 7;
            cp16_(abuf + sw128((uint32_t)(row * 128 + ch * 16)),
                  a_src + (size_t)(m0 + row) * K + kc * 64 + ch * 8);
            cp16_(bbuf + sw128((uint32_t)(row * 128 + ch * 16)),
                  w_src + (size_t)(n0 + row) * K + kc * 64 + ch * 8);
        }
    };

    float acc[2][8][4];
#pragma unroll
    for (int mf = 0; mf < 2; mf++)
#pragma unroll
        for (int nf = 0; nf < 8; nf++)
#pragma unroll
            for (int q = 0; q < 4; q++) acc[mf][nf][q] = 0.0f;

    prefetch(0, 0);
    CP_COMMIT();

    const int lrow = lane & 15;
    const int lch  = (lane >> 4) * 16;

    for (int c = 0; c < C; c++) {
        if (c + 1 < C) { prefetch(c + 1, (c + 1) & 1); CP_COMMIT(); CP_WAIT1(); }
        else           { CP_WAIT0(); }
        __syncthreads();

        char* abuf = smem + (c & 1) * 2 * PSTG;
        char* bbuf = abuf + PSTG;
        const uint32_t abase = smem_u32_(abuf);
        const uint32_t bbase = smem_u32_(bbuf);

#pragma unroll
        for (int k16 = 0; k16 < 4; k16++) {
            uint32_t afr[2][4];
#pragma unroll
            for (int mf = 0; mf < 2; mf++) {
                uint32_t addr = abase +
                    sw128((uint32_t)((wm * 32 + mf * 16 + lrow) * 128 + k16 * 32 + lch));
                LDMATRIX_X4(afr[mf][0], afr[mf][1], afr[mf][2], afr[mf][3], addr);
            }
#pragma unroll
            for (int nf2 = 0; nf2 < 4; nf2++) {
                uint32_t bm0, bm1, bm2, bm3;
                uint32_t addr = bbase +
                    sw128((uint32_t)((wn * 64 + nf2 * 16 + lrow) * 128 + k16 * 32 + lch));
                LDMATRIX_X4(bm0, bm1, bm2, bm3, addr);
#pragma unroll
                for (int mf = 0; mf < 2; mf++) {
                    MMA_BF16(acc[mf][2 * nf2 + 0], afr[mf], bm0, bm2);
                    MMA_BF16(acc[mf][2 * nf2 + 1], afr[mf], bm1, bm3);
                }
            }
        }
        __syncthreads();
    }

    // epilogue: write fp32 + bias directly to g_xp
    const int rrow = lane >> 2;
    const int cq   = (lane & 3) * 2;
#pragma unroll
    for (int mf = 0; mf < 2; mf++) {
        int m_lo = m0 + wm * 32 + mf * 16 + rrow;
#pragma unroll
        for (int nf = 0; nf < 8; nf++) {
            int nl = wn * 64 + nf * 8 + cq;
            float bv0 = bias_s[nl], bv1 = bias_s[nl + 1];
            float2 v0 = { acc[mf][nf][0] + bv0, acc[mf][nf][1] + bv1 };
            float2 v1 = { acc[mf][nf][2] + bv0, acc[mf][nf][3] + bv1 };
            *(float2*)(g_xp + (size_t)m_lo * G4 + n0 + nl)       = v0;
            *(float2*)(g_xp + (size_t)(m_lo + 8) * G4 + n0 + nl) = v1;
        }
    }
}

// ---------------- persistent LSTM layer kernel (unchanged from passing R3) ----------------
#define W2F_FLOATS (4 * 8 * 258 * 2)           // 16512
#define HS_FLOATS  (32 * 260)                  // 8320
#define PERSIST_SMEM_BYTES ((W2F_FLOATS + HS_FLOATS) * 4)

__global__ __launch_bounds__(256, 1) void lstm_persist_kernel(
    const float* __restrict__ Whh, int write_hs)
{
    extern __shared__ float smemf[];
    float* w2f = smemf;
    float* h_s = smemf + W2F_FLOATS;

    const int tid = threadIdx.x;
    const int jg  = tid & 7;
    const int bl  = tid >> 3;
    const int b0  = blockIdx.x * 32;
    const int j0  = blockIdx.y * 16;
    const int b   = b0 + bl;
    const int j   = j0 + 2 * jg;

    for (int idx = tid; idx < 4096; idx += 256) {
        int row = idx >> 6;
        int kq  = idx & 63;
        int g   = row >> 4;
        int jj  = row & 15;
        float4 v = *(const float4*)(Whh + (size_t)(g * HH + j0 + jj) * HH + kq * 4);
        int jp   = jj >> 1;
        int lane = jj & 1;
        float* dst = w2f + ((g * 8 + jp) * 258 + kq * 4) * 2 + lane;
        dst[0] = v.x; dst[2] = v.y; dst[4] = v.z; dst[6] = v.w;
    }
    __syncthreads();

    float c0 = 0.0f, c1 = 0.0f;

    for (int t = 0; t < TT; t++) {
        const float* __restrict__ hprev = g_h[t & 1];
        float* __restrict__ hnext       = g_h[(t & 1) ^ 1];

        unsigned long long accA[4], accB[4];
#pragma unroll
        for (int g = 0; g < 4; g++) { accA[g] = 0ull; accB[g] = 0ull; }

        if (t > 0) {
            for (int i = tid; i < 2048; i += 256) {
                int row = i >> 6;
                int kq  = i & 63;
                float4 v = __ldcg((const float4*)(hprev + (size_t)(b0 + row) * HH + kq * 4));
                *(float4*)&h_s[row * 260 + kq * 4] = v;
            }
            __syncthreads();

#pragma unroll 4
            for (int k = 0; k < HH; k += 4) {
                float4 hv = *(const float4*)&h_s[bl * 260 + k];
                unsigned long long h2a = bcast2_(hv.x);
                unsigned long long h2b = bcast2_(hv.y);
                unsigned long long h2c = bcast2_(hv.z);
                unsigned long long h2d = bcast2_(hv.w);
#pragma unroll
                for (int g = 0; g < 4; g++) {
                    const ulonglong2* wp =
                        (const ulonglong2*)(w2f + ((g * 8 + jg) * 258 + k) * 2);
                    ulonglong2 wA = wp[0];
                    ulonglong2 wB = wp[1];
                    fma2_(accA[g], h2a, wA.x);
                    fma2_(accB[g], h2b, wA.y);
                    fma2_(accA[g], h2c, wB.x);
                    fma2_(accB[g], h2d, wB.y);
                }
            }
        }

        float2 gate[4];
#pragma unroll
        for (int g = 0; g < 4; g++) {
            float2 a  = unpack2_(accA[g]);
            float2 bb = unpack2_(accB[g]);
            float2 xv = *(const float2*)(g_xp + ((size_t)b * TT + t) * G4 + g * HH + j);
            gate[g].x = a.x + bb.x + xv.x;
            gate[g].y = a.y + bb.y + xv.y;
        }
        float i0 = sigmoidf_(gate[0].x), i1 = sigmoidf_(gate[0].y);
        float f0 = sigmoidf_(gate[1].x), f1 = sigmoidf_(gate[1].y);
        float g0 = tanhf_   (gate[2].x), g1 = tanhf_   (gate[2].y);
        float o0 = sigmoidf_(gate[3].x), o1 = sigmoidf_(gate[3].y);
        c0 = f0 * c0 + i0 * g0;
        c1 = f1 * c1 + i1 * g1;
        float2 hv2;
        hv2.x = o0 * tanhf_(c0);
        hv2.y = o1 * tanhf_(c1);
        __stcg((float2*)(hnext + (size_t)b * HH + j), hv2);
        if (write_hs)
            *(float2*)(g_hs + ((size_t)b * TT + t) * HH + j) = hv2;

        __syncthreads();
        if (tid == 0) {
            __threadfence();
            unsigned cnt    = atomicAdd(&g_arrive, 1u) + 1u;
            unsigned target = ((cnt + NCTA - 1u) / NCTA) * NCTA;
            if (cnt == target) {
                g_release = cnt;
            } else {
                while ((int)(g_release - target) < 0) __nanosleep(32);
            }
            __threadfence();
        }
        __syncthreads();
    }
}

// ---------------- final classifier ----------------
__global__ __launch_bounds__(256) void fc_kernel(
    const float* __restrict__ fcW, const float* __restrict__ fcb,
    float* __restrict__ out)
{
    __shared__ float hrow[HH];
    const int b = blockIdx.x;
    const float* __restrict__ h = g_h[0];
    for (int k = threadIdx.x; k < HH; k += 256) hrow[k] = h[b * HH + k];
    __syncthreads();

    for (int c = threadIdx.x; c < CDIM; c += 256) {
        const float* __restrict__ w = fcW + (size_t)c * HH;
        float s = fcb[c];
#pragma unroll
        for (int k = 0; k < HH; k += 4) {
            float4 wv = *(const float4*)(w + k);
            s += hrow[k + 0] * wv.x;
            s += hrow[k + 1] * wv.y;
            s += hrow[k + 2] * wv.z;
            s += hrow[k + 3] * wv.w;
        }
        out[(size_t)b * CDIM + c] = s;
    }
}

// ---------------- launch ----------------
extern "C" void kernel_launch(void* const* d_in, const int* in_sizes, int n_in,
                              void* d_out, int out_size)
{
    const float* x    = (const float*)d_in[0];
    const float* Wih0 = (const float*)d_in[1];
    const float* Whh0 = (const float*)d_in[2];
    const float* bih0 = (const float*)d_in[3];
    const float* bhh0 = (const float*)d_in[4];
    const float* Wih1 = (const float*)d_in[5];
    const float* Whh1 = (const float*)d_in[6];
    const float* bih1 = (const float*)d_in[7];
    const float* bhh1 = (const float*)d_in[8];
    const float* fcW  = (const float*)d_in[9];
    const float* fcb  = (const float*)d_in[10];
    float* out = (float*)d_out;

    cudaFuncSetAttribute(lstm_persist_kernel,
                         cudaFuncAttributeMaxDynamicSharedMemorySize,
                         PERSIST_SMEM_BYTES);
    cudaFuncSetAttribute(proj_mma_kernel,
                         cudaFuncAttributeMaxDynamicSharedMemorySize,
                         PROJ_SMEM_TOTAL);

    const dim3 proj_grid(G4 / 128, (BB * TT) / 128);  // (8, 1024)
    const dim3 pers_grid(BB / 32, HH / 16);           // (8, 16) = 128 CTAs

    // ---- layer 0 ----
    {
        size_t n4x = (size_t)BB * TT * IDIM / 4;
        size_t n4w = (size_t)G4 * IDIM / 4;
        split_bf16_kernel<<<(unsigned)((n4x + 255) / 256), 256>>>(x, 0, 0, n4x);
        split_bf16_kernel<<<(unsigned)((n4w + 255) / 256), 256>>>(Wih0, 0, 1, n4w);
        proj_mma_kernel<<<proj_grid, 256, PROJ_SMEM_TOTAL>>>(bih0, bhh0, IDIM);
        lstm_persist_kernel<<<pers_grid, 256, PERSIST_SMEM_BYTES>>>(Whh0, 1);
    }

    // ---- layer 1 ----
    {
        size_t n4h = (size_t)BB * TT * HH / 4;
        size_t n4w = (size_t)G4 * HH / 4;
        split_bf16_kernel<<<(unsigned)((n4h + 255) / 256), 256>>>(nullptr, 1, 0, n4h);
        split_bf16_kernel<<<(unsigned)((n4w + 255) / 256), 256>>>(Wih1, 0, 1, n4w);
        proj_mma_kernel<<<proj_grid, 256, PROJ_SMEM_TOTAL>>>(bih1, bhh1, HH);
        lstm_persist_kernel<<<pers_grid, 256, PERSIST_SMEM_BYTES>>>(Whh1, 0);
    }

    // ---- classifier ----
    fc_kernel<<<BB, 256>>>(fcW, fcb, out);
}

// round 7
// speedup vs baseline: 1.1141x; 1.0250x over previous
#include <cuda_runtime.h>
#include <cuda_bf16.h>
#include <math.h>
#include <cstdint>

#define BB   256      // batch
#define TT   512      // time steps
#define IDIM 128      // input dim
#define HH   256      // hidden dim
#define CDIM 1000     // classes
#define G4   (4*HH)   // 1024 gate columns

// ---------------- scratch (static device allocations; no cudaMalloc) ----------------
// g_xp layout: [t][b][jp][g][2]  (jp = j>>1; 8 floats per (b,jp): g0j0,g0j1,g1j0,...)
__device__ float g_xp[(size_t)BB * TT * G4];
__device__ float g_hs[(size_t)BB * TT * HH];   // layer-0 hidden sequence [b][t][j]
__device__ float g_h[2][BB * HH];              // double-buffered hidden state
__device__ unsigned int          g_arrive2[8 * 32];   // per-group barrier (padded)
__device__ volatile unsigned int g_release2[8 * 32];

// bf16 split buffers for tensor-core projections
__device__ __nv_bfloat16 g_a_hi[(size_t)BB * TT * HH];
__device__ __nv_bfloat16 g_a_lo[(size_t)BB * TT * HH];
__device__ __nv_bfloat16 g_w_hi[(size_t)G4 * HH];
__device__ __nv_bfloat16 g_w_lo[(size_t)G4 * HH];

// ---------------- generic helpers ----------------
__device__ __forceinline__ float sigmoidf_(float x) {
    return 1.0f / (1.0f + __expf(-x));
}
__device__ __forceinline__ float tanhf_(float x) {
    float ax = fabsf(x);
    float e  = __expf(-2.0f * ax);
    float r  = (1.0f - e) / (1.0f + e);
    return copysignf(r, x);
}
__device__ __forceinline__ void fma2_(unsigned long long& d,
                                      unsigned long long a,
                                      unsigned long long b) {
    asm("fma.rn.f32x2 %0, %1, %2, %3;" : "=l"(d) : "l"(a), "l"(b), "l"(d));
}
__device__ __forceinline__ unsigned long long bcast2_(float x) {
    unsigned long long r;
    asm("mov.b64 %0, {%1, %1};" : "=l"(r) : "f"(x));
    return r;
}
__device__ __forceinline__ float2 unpack2_(unsigned long long v) {
    float2 r;
    asm("mov.b64 {%0, %1}, %2;" : "=f"(r.x), "=f"(r.y) : "l"(v));
    return r;
}
__device__ __forceinline__ uint32_t smem_u32_(const void* p) {
    uint32_t a;
    asm("{ .reg .u64 t; cvta.to.shared.u64 t, %1; cvt.u32.u64 %0, t; }"
        : "=r"(a) : "l"(p));
    return a;
}
static __device__ __forceinline__ uint32_t sw128(uint32_t off) {
    return off ^ ((off >> 3) & 0x70);
}

// cp.async (sm_80+; base-target safe)
__device__ __forceinline__ void cp16_(void* smem_dst, const void* gsrc) {
    uint32_t d = smem_u32_(smem_dst);
    asm volatile("cp.async.cg.shared.global [%0], [%1], 16;" :: "r"(d), "l"(gsrc));
}
#define CP_COMMIT() asm volatile("cp.async.commit_group;" ::: "memory")
#define CP_WAIT1()  asm volatile("cp.async.wait_group 1;" ::: "memory")
#define CP_WAIT0()  asm volatile("cp.async.wait_group 0;" ::: "memory")

// ldmatrix x4 (sm_75+)
#define LDMATRIX_X4(r0, r1, r2, r3, addr) \
    asm volatile("ldmatrix.sync.aligned.m8n8.x4.shared.b16 {%0,%1,%2,%3}, [%4];" \
                 : "=r"(r0), "=r"(r1), "=r"(r2), "=r"(r3) : "r"(addr))

// mma m16n8k16 bf16 (sm_80+)
#define MMA_BF16(d, a, b0v, b1v) \
    asm volatile("mma.sync.aligned.m16n8k16.row.col.f32.bf16.bf16.f32 " \
                 "{%0,%1,%2,%3}, {%4,%5,%6,%7}, {%8,%9}, {%0,%1,%2,%3};" \
                 : "+f"((d)[0]), "+f"((d)[1]), "+f"((d)[2]), "+f"((d)[3]) \
                 : "r"((a)[0]), "r"((a)[1]), "r"((a)[2]), "r"((a)[3]), \
                   "r"(b0v), "r"(b1v))

// ---------------- bf16 split conversion ----------------
__global__ __launch_bounds__(256) void split_bf16_kernel(
    const float* __restrict__ src_ext, int use_hs, int to_w, size_t n4)
{
    size_t i = (size_t)blockIdx.x * blockDim.x + threadIdx.x;
    if (i >= n4) return;
    const float4* s = (const float4*)(use_hs ? (const float*)g_hs : src_ext);
    __nv_bfloat162* dh = (__nv_bfloat162*)(to_w ? g_w_hi : g_a_hi);
    __nv_bfloat162* dl = (__nv_bfloat162*)(to_w ? g_w_lo : g_a_lo);
    float4 v = s[i];
    __nv_bfloat16 h0 = __float2bfloat16(v.x);
    __nv_bfloat16 h1 = __float2bfloat16(v.y);
    __nv_bfloat16 h2 = __float2bfloat16(v.z);
    __nv_bfloat16 h3 = __float2bfloat16(v.w);
    __nv_bfloat16 l0 = __float2bfloat16(v.x - __bfloat162float(h0));
    __nv_bfloat16 l1 = __float2bfloat16(v.y - __bfloat162float(h1));
    __nv_bfloat16 l2 = __float2bfloat16(v.z - __bfloat162float(h2));
    __nv_bfloat16 l3 = __float2bfloat16(v.w - __bfloat162float(h3));
    dh[i * 2 + 0] = __halves2bfloat162(h0, h1);
    dh[i * 2 + 1] = __halves2bfloat162(h2, h3);
    dl[i * 2 + 0] = __halves2bfloat162(l0, l1);
    dl[i * 2 + 1] = __halves2bfloat162(l2, l3);
}

// ---------------- HMMA projection ----------------
// Output tile: 128(M) x 128(N). 256 threads = 8 warps, 4(m) x 2(n); warp tile 32x64.
// K pipeline: 3 splits (hi*hi, w_lo, a_lo) x (K/64) chunks; BK=64 bf16, SW128 SMEM.
#define PSTG 16384
#define PROJ_SMEM_TOTAL (4 * PSTG + 512)

__global__ __launch_bounds__(256) void proj_mma_kernel(
    const float* __restrict__ b1, const float* __restrict__ b2, int K)
{
    extern __shared__ char smem[];
    float* bias_s = (float*)(smem + 4 * PSTG);

    const int tid  = threadIdx.x;
    const int lane = tid & 31;
    const int w    = tid >> 5;
    const int wm   = w & 3;
    const int wn   = w >> 2;
    const int n0   = blockIdx.x * 128;
    const int m0   = blockIdx.y * 128;

    if (tid < 128) bias_s[tid] = b1[n0 + tid] + b2[n0 + tid];

    const int kchunks = K >> 6;
    const int C = 3 * kchunks;

    auto prefetch = [&](int c, int stage) {
        const int s  = c / kchunks;
        const int kc = c % kchunks;
        const __nv_bfloat16* a_src = (s == 2) ? g_a_lo : g_a_hi;
        const __nv_bfloat16* w_src = (s == 1) ? g_w_lo : g_w_hi;
        char* abuf = smem + stage * 2 * PSTG;
        char* bbuf = abuf + PSTG;
#pragma unroll
        for (int i = 0; i < 4; i++) {
            int id  = tid + i * 256;
            int row = id >> 3;
            int ch  = id & 7;
            cp16_(abuf + sw128((uint32_t)(row * 128 + ch * 16)),
                  a_src + (size_t)(m0 + row) * K + kc * 64 + ch * 8);
            cp16_(bbuf + sw128((uint32_t)(row * 128 + ch * 16)),
                  w_src + (size_t)(n0 + row) * K + kc * 64 + ch * 8);
        }
    };

    float acc[2][8][4];
#pragma unroll
    for (int mf = 0; mf < 2; mf++)
#pragma unroll
        for (int nf = 0; nf < 8; nf++)
#pragma unroll
            for (int q = 0; q < 4; q++) acc[mf][nf][q] = 0.0f;

    prefetch(0, 0);
    CP_COMMIT();

    const int lrow = lane & 15;
    const int lch  = (lane >> 4) * 16;

    for (int c = 0; c < C; c++) {
        if (c + 1 < C) { prefetch(c + 1, (c + 1) & 1); CP_COMMIT(); CP_WAIT1(); }
        else           { CP_WAIT0(); }
        __syncthreads();

        char* abuf = smem + (c & 1) * 2 * PSTG;
        char* bbuf = abuf + PSTG;
        const uint32_t abase = smem_u32_(abuf);
        const uint32_t bbase = smem_u32_(bbuf);

#pragma unroll
        for (int k16 = 0; k16 < 4; k16++) {
            uint32_t afr[2][4];
#pragma unroll
            for (int mf = 0; mf < 2; mf++) {
                uint32_t addr = abase +
                    sw128((uint32_t)((wm * 32 + mf * 16 + lrow) * 128 + k16 * 32 + lch));
                LDMATRIX_X4(afr[mf][0], afr[mf][1], afr[mf][2], afr[mf][3], addr);
            }
#pragma unroll
            for (int nf2 = 0; nf2 < 4; nf2++) {
                uint32_t bm0, bm1, bm2, bm3;
                uint32_t addr = bbase +
                    sw128((uint32_t)((wn * 64 + nf2 * 16 + lrow) * 128 + k16 * 32 + lch));
                LDMATRIX_X4(bm0, bm1, bm2, bm3, addr);
#pragma unroll
                for (int mf = 0; mf < 2; mf++) {
                    MMA_BF16(acc[mf][2 * nf2 + 0], afr[mf], bm0, bm2);
                    MMA_BF16(acc[mf][2 * nf2 + 1], afr[mf], bm1, bm3);
                }
            }
        }
        __syncthreads();
    }

    // epilogue: write fp32 + bias into time-major interleaved g_xp:
    //   offset = ((t*BB + b)*G4) + (j>>1)*8 + g*2   (float2 per (gate, j-pair))
    const int rrow = lane >> 2;
    const int cq   = (lane & 3) * 2;
#pragma unroll
    for (int mf = 0; mf < 2; mf++) {
#pragma unroll
        for (int rr = 0; rr < 2; rr++) {
            int m = m0 + wm * 32 + mf * 16 + rrow + rr * 8;
            int t = m & (TT - 1);
            int b = m >> 9;                       // m / TT
            float* obase = g_xp + ((size_t)t * BB + b) * G4;
#pragma unroll
            for (int nf = 0; nf < 8; nf++) {
                int nl = wn * 64 + nf * 8 + cq;
                int n  = n0 + nl;
                int g  = n >> 8;
                int jj = n & 255;
                float bv0 = bias_s[nl], bv1 = bias_s[nl + 1];
                float2 v = { acc[mf][nf][2 * rr + 0] + bv0,
                             acc[mf][nf][2 * rr + 1] + bv1 };
                *(float2*)(obase + (jj >> 1) * 8 + g * 2) = v;
            }
        }
    }
}

// ---------------- persistent LSTM layer kernel ----------------
// Grid (8, 16): blockIdx.x = batch group of 32 (barrier group), blockIdx.y = j slice of 16.
// 256 threads: jg = tid&7 (j-pair), bl = tid>>3 (local batch).
#define W2F_FLOATS (4 * 8 * 258 * 2)           // 16512
#define HS_FLOATS  (32 * 260)                  // 8320
#define PERSIST_SMEM_BYTES ((W2F_FLOATS + HS_FLOATS) * 4)

__global__ __launch_bounds__(256, 1) void lstm_persist_kernel(
    const float* __restrict__ Whh, int write_hs)
{
    extern __shared__ float smemf[];
    float* w2f = smemf;
    float* h_s = smemf + W2F_FLOATS;

    const int tid = threadIdx.x;
    const int jg  = tid & 7;
    const int bl  = tid >> 3;
    const int b0  = blockIdx.x * 32;
    const int j0  = blockIdx.y * 16;
    const int b   = b0 + bl;
    const int j   = j0 + 2 * jg;
    const int jp  = j >> 1;

    for (int idx = tid; idx < 4096; idx += 256) {
        int row = idx >> 6;
        int kq  = idx & 63;
        int g   = row >> 4;
        int jj  = row & 15;
        float4 v = *(const float4*)(Whh + (size_t)(g * HH + j0 + jj) * HH + kq * 4);
        int jpp  = jj >> 1;
        int lane = jj & 1;
        float* dst = w2f + ((g * 8 + jpp) * 258 + kq * 4) * 2 + lane;
        dst[0] = v.x; dst[2] = v.y; dst[4] = v.z; dst[6] = v.w;
    }
    __syncthreads();

    float c0 = 0.0f, c1 = 0.0f;

    for (int t = 0; t < TT; t++) {
        const float* __restrict__ hprev = g_h[t & 1];
        float* __restrict__ hnext       = g_h[(t & 1) ^ 1];

        // ---- issue xp loads FIRST (coalesced, time-major) so DRAM latency hides
        const float* xp = g_xp + ((size_t)t * BB + b) * G4 + (size_t)jp * 8;
        float4 xv0 = *(const float4*)(xp);      // g0(j,j+1), g1(j,j+1)
        float4 xv1 = *(const float4*)(xp + 4);  // g2(j,j+1), g3(j,j+1)

        unsigned long long accA[4], accB[4];
#pragma unroll
        for (int g = 0; g < 4; g++) { accA[g] = 0ull; accB[g] = 0ull; }

        if (t > 0) {
            for (int i = tid; i < 2048; i += 256) {
                int row = i >> 6;
                int kq  = i & 63;
                float4 v = __ldcg((const float4*)(hprev + (size_t)(b0 + row) * HH + kq * 4));
                *(float4*)&h_s[row * 260 + kq * 4] = v;
            }
            __syncthreads();

#pragma unroll 4
            for (int k = 0; k < HH; k += 4) {
                float4 hv = *(const float4*)&h_s[bl * 260 + k];
                unsigned long long h2a = bcast2_(hv.x);
                unsigned long long h2b = bcast2_(hv.y);
                unsigned long long h2c = bcast2_(hv.z);
                unsigned long long h2d = bcast2_(hv.w);
#pragma unroll
                for (int g = 0; g < 4; g++) {
                    const ulonglong2* wp =
                        (const ulonglong2*)(w2f + ((g * 8 + jg) * 258 + k) * 2);
                    ulonglong2 wA = wp[0];
                    ulonglong2 wB = wp[1];
                    fma2_(accA[g], h2a, wA.x);
                    fma2_(accB[g], h2b, wA.y);
                    fma2_(accA[g], h2c, wB.x);
                    fma2_(accB[g], h2d, wB.y);
                }
            }
        }

        float xg[4][2] = { {xv0.x, xv0.y}, {xv0.z, xv0.w},
                           {xv1.x, xv1.y}, {xv1.z, xv1.w} };
        float2 gate[4];
#pragma unroll
        for (int g = 0; g < 4; g++) {
            float2 a  = unpack2_(accA[g]);
            float2 bb = unpack2_(accB[g]);
            gate[g].x = a.x + bb.x + xg[g][0];
            gate[g].y = a.y + bb.y + xg[g][1];
        }
        float i0 = sigmoidf_(gate[0].x), i1 = sigmoidf_(gate[0].y);
        float f0 = sigmoidf_(gate[1].x), f1 = sigmoidf_(gate[1].y);
        float g0 = tanhf_   (gate[2].x), g1 = tanhf_   (gate[2].y);
        float o0 = sigmoidf_(gate[3].x), o1 = sigmoidf_(gate[3].y);
        c0 = f0 * c0 + i0 * g0;
        c1 = f1 * c1 + i1 * g1;
        float2 hv2;
        hv2.x = o0 * tanhf_(c0);
        hv2.y = o1 * tanhf_(c1);
        __stcg((float2*)(hnext + (size_t)b * HH + j), hv2);
        if (write_hs)
            *(float2*)(g_hs + ((size_t)b * TT + t) * HH + j) = hv2;

        // ---- per-batch-group barrier (16 CTAs; cumulative counters, tight spin)
        __syncthreads();
        if (tid == 0) {
            __threadfence();
            unsigned* arr = &g_arrive2[blockIdx.x * 32];
            volatile unsigned* rel = &g_release2[blockIdx.x * 32];
            unsigned cnt    = atomicAdd(arr, 1u) + 1u;
            unsigned target = ((cnt + 15u) >> 4) << 4;
            if (cnt == target) {
                *rel = cnt;
            } else {
                while ((int)(*rel - target) < 0) { }
            }
            __threadfence();
        }
        __syncthreads();
    }
}

// ---------------- final classifier ----------------
__global__ __launch_bounds__(256) void fc_kernel(
    const float* __restrict__ fcW, const float* __restrict__ fcb,
    float* __restrict__ out)
{
    __shared__ float hrow[HH];
    const int b = blockIdx.x;
    const float* __restrict__ h = g_h[0];
    for (int k = threadIdx.x; k < HH; k += 256) hrow[k] = h[b * HH + k];
    __syncthreads();

    for (int c = threadIdx.x; c < CDIM; c += 256) {
        const float* __restrict__ w = fcW + (size_t)c * HH;
        float s = fcb[c];
#pragma unroll
        for (int k = 0; k < HH; k += 4) {
            float4 wv = *(const float4*)(w + k);
            s += hrow[k + 0] * wv.x;
            s += hrow[k + 1] * wv.y;
            s += hrow[k + 2] * wv.z;
            s += hrow[k + 3] * wv.w;
        }
        out[(size_t)b * CDIM + c] = s;
    }
}

// ---------------- launch ----------------
extern "C" void kernel_launch(void* const* d_in, const int* in_sizes, int n_in,
                              void* d_out, int out_size)
{
    const float* x    = (const float*)d_in[0];
    const float* Wih0 = (const float*)d_in[1];
    const float* Whh0 = (const float*)d_in[2];
    const float* bih0 = (const float*)d_in[3];
    const float* bhh0 = (const float*)d_in[4];
    const float* Wih1 = (const float*)d_in[5];
    const float* Whh1 = (const float*)d_in[6];
    const float* bih1 = (const float*)d_in[7];
    const float* bhh1 = (const float*)d_in[8];
    const float* fcW  = (const float*)d_in[9];
    const float* fcb  = (const float*)d_in[10];
    float* out = (float*)d_out;

    cudaFuncSetAttribute(lstm_persist_kernel,
                         cudaFuncAttributeMaxDynamicSharedMemorySize,
                         PERSIST_SMEM_BYTES);
    cudaFuncSetAttribute(proj_mma_kernel,
                         cudaFuncAttributeMaxDynamicSharedMemorySize,
                         PROJ_SMEM_TOTAL);

    const dim3 proj_grid(G4 / 128, (BB * TT) / 128);  // (8, 1024)
    const dim3 pers_grid(BB / 32, HH / 16);           // (8, 16) = 128 CTAs

    // ---- layer 0 ----
    {
        size_t n4x = (size_t)BB * TT * IDIM / 4;
        size_t n4w = (size_t)G4 * IDIM / 4;
        split_bf16_kernel<<<(unsigned)((n4x + 255) / 256), 256>>>(x, 0, 0, n4x);
        split_bf16_kernel<<<(unsigned)((n4w + 255) / 256), 256>>>(Wih0, 0, 1, n4w);
        proj_mma_kernel<<<proj_grid, 256, PROJ_SMEM_TOTAL>>>(bih0, bhh0, IDIM);
        lstm_persist_kernel<<<pers_grid, 256, PERSIST_SMEM_BYTES>>>(Whh0, 1);
    }

    // ---- layer 1 ----
    {
        size_t n4h = (size_t)BB * TT * HH / 4;
        size_t n4w = (size_t)G4 * HH / 4;
        split_bf16_kernel<<<(unsigned)((n4h + 255) / 256), 256>>>(nullptr, 1, 0, n4h);
        split_bf16_kernel<<<(unsigned)((n4w + 255) / 256), 256>>>(Wih1, 0, 1, n4w);
        proj_mma_kernel<<<proj_grid, 256, PROJ_SMEM_TOTAL>>>(bih1, bhh1, HH);
        lstm_persist_kernel<<<pers_grid, 256, PERSIST_SMEM_BYTES>>>(Whh1, 0);
    }

    // ---- classifier ----
    fc_kernel<<<BB, 256>>>(fcW, fcb, out);
}

// round 8
// speedup vs baseline: 2.0557x; 1.8451x over previous
#include <cuda_runtime.h>
#include <cuda_bf16.h>
#include <math.h>
#include <cstdint>

#define BB   256      // batch
#define TT   512      // time steps
#define IDIM 128      // input dim
#define HH   256      // hidden dim
#define CDIM 1000     // classes
#define G4   (4*HH)   // 1024 gate columns

// ---------------- scratch (static device allocations; no cudaMalloc) ----------------
// g_xp layout: [t][b][jp][g][2]  (jp = j>>1; 8 floats per (b,jp))
__device__ float g_xp[(size_t)BB * TT * G4];
__device__ float g_hs[(size_t)BB * TT * HH];   // layer-0 hidden sequence [b][t][j]
__device__ float g_h[2][BB * HH];              // double-buffered hidden state
__device__ unsigned int          g_arrive2[8 * 32];   // per-group barrier (padded)
__device__ volatile unsigned int g_release2[8 * 32];

// bf16 split buffers for tensor-core projections
__device__ __nv_bfloat16 g_a_hi[(size_t)BB * TT * HH];
__device__ __nv_bfloat16 g_a_lo[(size_t)BB * TT * HH];
__device__ __nv_bfloat16 g_w_hi[(size_t)G4 * HH];
__device__ __nv_bfloat16 g_w_lo[(size_t)G4 * HH];

// ---------------- generic helpers ----------------
__device__ __forceinline__ float sigmoidf_(float x) {
    return 1.0f / (1.0f + __expf(-x));
}
__device__ __forceinline__ float tanhf_(float x) {
    float ax = fabsf(x);
    float e  = __expf(-2.0f * ax);
    float r  = (1.0f - e) / (1.0f + e);
    return copysignf(r, x);
}
__device__ __forceinline__ uint32_t smem_u32_(const void* p) {
    uint32_t a;
    asm("{ .reg .u64 t; cvta.to.shared.u64 t, %1; cvt.u32.u64 %0, t; }"
        : "=r"(a) : "l"(p));
    return a;
}
static __device__ __forceinline__ uint32_t sw128(uint32_t off) {
    return off ^ ((off >> 3) & 0x70);
}

// cp.async (sm_80+; base-target safe)
__device__ __forceinline__ void cp16_(void* smem_dst, const void* gsrc) {
    uint32_t d = smem_u32_(smem_dst);
    asm volatile("cp.async.cg.shared.global [%0], [%1], 16;" :: "r"(d), "l"(gsrc));
}
#define CP_COMMIT() asm volatile("cp.async.commit_group;" ::: "memory")
#define CP_WAIT1()  asm volatile("cp.async.wait_group 1;" ::: "memory")
#define CP_WAIT0()  asm volatile("cp.async.wait_group 0;" ::: "memory")

// ldmatrix x4 (sm_75+)
#define LDMATRIX_X4(r0, r1, r2, r3, addr) \
    asm volatile("ldmatrix.sync.aligned.m8n8.x4.shared.b16 {%0,%1,%2,%3}, [%4];" \
                 : "=r"(r0), "=r"(r1), "=r"(r2), "=r"(r3) : "r"(addr))

// mma m16n8k16 bf16 (sm_80+)
#define MMA_BF16(d, a, b0v, b1v) \
    asm volatile("mma.sync.aligned.m16n8k16.row.col.f32.bf16.bf16.f32 " \
                 "{%0,%1,%2,%3}, {%4,%5,%6,%7}, {%8,%9}, {%0,%1,%2,%3};" \
                 : "+f"((d)[0]), "+f"((d)[1]), "+f"((d)[2]), "+f"((d)[3]) \
                 : "r"((a)[0]), "r"((a)[1]), "r"((a)[2]), "r"((a)[3]), \
                   "r"(b0v), "r"(b1v))

// ---------------- bf16 split conversion ----------------
__global__ __launch_bounds__(256) void split_bf16_kernel(
    const float* __restrict__ src_ext, int use_hs, int to_w, size_t n4)
{
    size_t i = (size_t)blockIdx.x * blockDim.x + threadIdx.x;
    if (i >= n4) return;
    const float4* s = (const float4*)(use_hs ? (const float*)g_hs : src_ext);
    __nv_bfloat162* dh = (__nv_bfloat162*)(to_w ? g_w_hi : g_a_hi);
    __nv_bfloat162* dl = (__nv_bfloat162*)(to_w ? g_w_lo : g_a_lo);
    float4 v = s[i];
    __nv_bfloat16 h0 = __float2bfloat16(v.x);
    __nv_bfloat16 h1 = __float2bfloat16(v.y);
    __nv_bfloat16 h2 = __float2bfloat16(v.z);
    __nv_bfloat16 h3 = __float2bfloat16(v.w);
    __nv_bfloat16 l0 = __float2bfloat16(v.x - __bfloat162float(h0));
    __nv_bfloat16 l1 = __float2bfloat16(v.y - __bfloat162float(h1));
    __nv_bfloat16 l2 = __float2bfloat16(v.z - __bfloat162float(h2));
    __nv_bfloat16 l3 = __float2bfloat16(v.w - __bfloat162float(h3));
    dh[i * 2 + 0] = __halves2bfloat162(h0, h1);
    dh[i * 2 + 1] = __halves2bfloat162(h2, h3);
    dl[i * 2 + 0] = __halves2bfloat162(l0, l1);
    dl[i * 2 + 1] = __halves2bfloat162(l2, l3);
}

// ---------------- HMMA projection (unchanged from passing R7) ----------------
#define PSTG 16384
#define PROJ_SMEM_TOTAL (4 * PSTG + 512)

__global__ __launch_bounds__(256) void proj_mma_kernel(
    const float* __restrict__ b1, const float* __restrict__ b2, int K)
{
    extern __shared__ char smem[];
    float* bias_s = (float*)(smem + 4 * PSTG);

    const int tid  = threadIdx.x;
    const int lane = tid & 31;
    const int w    = tid >> 5;
    const int wm   = w & 3;
    const int wn   = w >> 2;
    const int n0   = blockIdx.x * 128;
    const int m0   = blockIdx.y * 128;

    if (tid < 128) bias_s[tid] = b1[n0 + tid] + b2[n0 + tid];

    const int kchunks = K >> 6;
    const int C = 3 * kchunks;

    auto prefetch = [&](int c, int stage) {
        const int s  = c / kchunks;
        const int kc = c % kchunks;
        const __nv_bfloat16* a_src = (s == 2) ? g_a_lo : g_a_hi;
        const __nv_bfloat16* w_src = (s == 1) ? g_w_lo : g_w_hi;
        char* abuf = smem + stage * 2 * PSTG;
        char* bbuf = abuf + PSTG;
#pragma unroll
        for (int i = 0; i < 4; i++) {
            int id  = tid + i * 256;
            int row = id >> 3;
            int ch  = id & 7;
            cp16_(abuf + sw128((uint32_t)(row * 128 + ch * 16)),
                  a_src + (size_t)(m0 + row) * K + kc * 64 + ch * 8);
            cp16_(bbuf + sw128((uint32_t)(row * 128 + ch * 16)),
                  w_src + (size_t)(n0 + row) * K + kc * 64 + ch * 8);
        }
    };

    float acc[2][8][4];
#pragma unroll
    for (int mf = 0; mf < 2; mf++)
#pragma unroll
        for (int nf = 0; nf < 8; nf++)
#pragma unroll
            for (int q = 0; q < 4; q++) acc[mf][nf][q] = 0.0f;

    prefetch(0, 0);
    CP_COMMIT();

    const int lrow = lane & 15;
    const int lch  = (lane >> 4) * 16;

    for (int c = 0; c < C; c++) {
        if (c + 1 < C) { prefetch(c + 1, (c + 1) & 1); CP_COMMIT(); CP_WAIT1(); }
        else           { CP_WAIT0(); }
        __syncthreads();

        char* abuf = smem + (c & 1) * 2 * PSTG;
        char* bbuf = abuf + PSTG;
        const uint32_t abase = smem_u32_(abuf);
        const uint32_t bbase = smem_u32_(bbuf);

#pragma unroll
        for (int k16 = 0; k16 < 4; k16++) {
            uint32_t afr[2][4];
#pragma unroll
            for (int mf = 0; mf < 2; mf++) {
                uint32_t addr = abase +
                    sw128((uint32_t)((wm * 32 + mf * 16 + lrow) * 128 + k16 * 32 + lch));
                LDMATRIX_X4(afr[mf][0], afr[mf][1], afr[mf][2], afr[mf][3], addr);
            }
#pragma unroll
            for (int nf2 = 0; nf2 < 4; nf2++) {
                uint32_t bm0, bm1, bm2, bm3;
                uint32_t addr = bbase +
                    sw128((uint32_t)((wn * 64 + nf2 * 16 + lrow) * 128 + k16 * 32 + lch));
                LDMATRIX_X4(bm0, bm1, bm2, bm3, addr);
#pragma unroll
                for (int mf = 0; mf < 2; mf++) {
                    MMA_BF16(acc[mf][2 * nf2 + 0], afr[mf], bm0, bm2);
                    MMA_BF16(acc[mf][2 * nf2 + 1], afr[mf], bm1, bm3);
                }
            }
        }
        __syncthreads();
    }

    const int rrow = lane >> 2;
    const int cq   = (lane & 3) * 2;
#pragma unroll
    for (int mf = 0; mf < 2; mf++) {
#pragma unroll
        for (int rr = 0; rr < 2; rr++) {
            int m = m0 + wm * 32 + mf * 16 + rrow + rr * 8;
            int t = m & (TT - 1);
            int b = m >> 9;
            float* obase = g_xp + ((size_t)t * BB + b) * G4;
#pragma unroll
            for (int nf = 0; nf < 8; nf++) {
                int nl = wn * 64 + nf * 8 + cq;
                int n  = n0 + nl;
                int g  = n >> 8;
                int jj = n & 255;
                float bv0 = bias_s[nl], bv1 = bias_s[nl + 1];
                float2 v = { acc[mf][nf][2 * rr + 0] + bv0,
                             acc[mf][nf][2 * rr + 1] + bv1 };
                *(float2*)(obase + (jj >> 1) * 8 + g * 2) = v;
            }
        }
    }
}

// ---------------- persistent LSTM layer kernel (HMMA recurrence) ----------------
// Grid (8, 16): blockIdx.x = batch group of 32 (barrier group), blockIdx.y = j slice of 16.
// CTA output per step: 32 batches x 64 gate-cols (col = g*16 + jl).
// SMEM planes use 576B row stride: bits[9:7] of r*576 form a permutation over 8
// consecutive rows -> SW128 twiddle distinct per row -> conflict-free ldmatrix.
#define WPLANE 36864                    // 64 rows x 576B
#define HPLANE 18432                    // 32 rows x 576B
#define GBOFF  (2 * WPLANE + 2 * HPLANE)        // 110592
#define PERSIST_SMEM_BYTES (GBOFF + 2 * 32 * 64 * 4)  // 126976

__global__ __launch_bounds__(256, 1) void lstm_persist_kernel(
    const float* __restrict__ Whh, int write_hs)
{
    extern __shared__ char smem[];
    char* w_hi = smem;
    char* w_lo = smem + WPLANE;
    char* h_hi = smem + 2 * WPLANE;
    char* h_lo = smem + 2 * WPLANE + HPLANE;
    float* gb  = (float*)(smem + GBOFF);     // [khalf][32][64]

    const int tid  = threadIdx.x;
    const int lane = tid & 31;
    const int wid  = tid >> 5;
    const int ns   = wid & 3;        // gate slice (n16)
    const int kh   = wid >> 2;       // k half (0: k<128, 1: k>=128)
    const int jg   = tid & 7;        // j pair (elementwise role)
    const int bl   = tid >> 3;       // local batch (elementwise role)
    const int b0   = blockIdx.x * 32;
    const int j0   = blockIdx.y * 16;
    const int b    = b0 + bl;
    const int j    = j0 + 2 * jg;
    const int jp   = j >> 1;

    // ---- load + split Whh slice into swizzled SMEM bf16 planes
    // row n = g*16 + jl  ->  Whh row g*HH + j0 + jl ; 64 rows x 256 cols
    for (int i = tid; i < 64 * 64; i += 256) {
        int row = i >> 6, kq = i & 63;
        int g = row >> 4, jl = row & 15;
        float4 v = *(const float4*)(Whh + (size_t)(g * HH + j0 + jl) * HH + kq * 4);
        __nv_bfloat16 a0 = __float2bfloat16(v.x);
        __nv_bfloat16 a1 = __float2bfloat16(v.y);
        __nv_bfloat16 a2 = __float2bfloat16(v.z);
        __nv_bfloat16 a3 = __float2bfloat16(v.w);
        __nv_bfloat162 hiA = __halves2bfloat162(a0, a1);
        __nv_bfloat162 hiB = __halves2bfloat162(a2, a3);
        __nv_bfloat162 loA = __halves2bfloat162(
            __float2bfloat16(v.x - __bfloat162float(a0)),
            __float2bfloat16(v.y - __bfloat162float(a1)));
        __nv_bfloat162 loB = __halves2bfloat162(
            __float2bfloat16(v.z - __bfloat162float(a2)),
            __float2bfloat16(v.w - __bfloat162float(a3)));
        uint32_t off = sw128((uint32_t)(row * 576 + kq * 8));
        *(__nv_bfloat162*)(w_hi + off)     = hiA;
        *(__nv_bfloat162*)(w_hi + off + 4) = hiB;
        *(__nv_bfloat162*)(w_lo + off)     = loA;
        *(__nv_bfloat162*)(w_lo + off + 4) = loB;
    }
    __syncthreads();

    const uint32_t whi_b = smem_u32_(w_hi);
    const uint32_t wlo_b = smem_u32_(w_lo);
    const uint32_t hhi_b = smem_u32_(h_hi);
    const uint32_t hlo_b = smem_u32_(h_lo);
    const int lrow = lane & 15;
    const int lch  = (lane >> 4) * 16;

    float c0 = 0.0f, c1 = 0.0f;

    for (int t = 0; t < TT; t++) {
        const float* __restrict__ hprev = g_h[t & 1];
        float* __restrict__ hnext       = g_h[(t & 1) ^ 1];

        // xp loads first (coalesced, time-major) -> DRAM latency hides under step
        const float* xp = g_xp + ((size_t)t * BB + b) * G4 + (size_t)jp * 8;
        float4 xv0 = *(const float4*)(xp);
        float4 xv1 = *(const float4*)(xp + 4);

        if (t > 0) {
            // ---- stage h (L1-bypass) + Dekker split into swizzled bf16 planes
            for (int i = tid; i < 32 * 64; i += 256) {
                int row = i >> 6, kq = i & 63;
                float4 v = __ldcg((const float4*)(hprev + (size_t)(b0 + row) * HH + kq * 4));
                __nv_bfloat16 a0 = __float2bfloat16(v.x);
                __nv_bfloat16 a1 = __float2bfloat16(v.y);
                __nv_bfloat16 a2 = __float2bfloat16(v.z);
                __nv_bfloat16 a3 = __float2bfloat16(v.w);
                __nv_bfloat162 hiA = __halves2bfloat162(a0, a1);
                __nv_bfloat162 hiB = __halves2bfloat162(a2, a3);
                __nv_bfloat162 loA = __halves2bfloat162(
                    __float2bfloat16(v.x - __bfloat162float(a0)),
                    __float2bfloat16(v.y - __bfloat162float(a1)));
                __nv_bfloat162 loB = __halves2bfloat162(
                    __float2bfloat16(v.z - __bfloat162float(a2)),
                    __float2bfloat16(v.w - __bfloat162float(a3)));
                uint32_t off = sw128((uint32_t)(row * 576 + kq * 8));
                *(__nv_bfloat162*)(h_hi + off)     = hiA;
                *(__nv_bfloat162*)(h_hi + off + 4) = hiB;
                *(__nv_bfloat162*)(h_lo + off)     = loA;
                *(__nv_bfloat162*)(h_lo + off + 4) = loB;
            }
            __syncthreads();

            // ---- HMMA: warp = (gate n16 slice ns) x (k half kh); 3 Dekker splits
            float acc[2][2][4];
#pragma unroll
            for (int mf = 0; mf < 2; mf++)
#pragma unroll
                for (int nf = 0; nf < 2; nf++)
#pragma unroll
                    for (int q = 0; q < 4; q++) acc[mf][nf][q] = 0.0f;

#pragma unroll
            for (int k16 = 0; k16 < 8; k16++) {
                const uint32_t kb = (uint32_t)(kh * 256 + k16 * 32 + lch);
                uint32_t ahi[2][4], alo[2][4];
#pragma unroll
                for (int mf = 0; mf < 2; mf++) {
                    uint32_t roff = sw128((uint32_t)((mf * 16 + lrow) * 576) + kb);
                    LDMATRIX_X4(ahi[mf][0], ahi[mf][1], ahi[mf][2], ahi[mf][3],
                                hhi_b + roff);
                    LDMATRIX_X4(alo[mf][0], alo[mf][1], alo[mf][2], alo[mf][3],
                                hlo_b + roff);
                }
                uint32_t woff = sw128((uint32_t)((ns * 16 + lrow) * 576) + kb);
                uint32_t bh0, bh1, bh2, bh3, bl0, bl1, bl2, bl3;
                LDMATRIX_X4(bh0, bh1, bh2, bh3, whi_b + woff);
                LDMATRIX_X4(bl0, bl1, bl2, bl3, wlo_b + woff);
#pragma unroll
                for (int mf = 0; mf < 2; mf++) {
                    MMA_BF16(acc[mf][0], ahi[mf], bh0, bh2);
                    MMA_BF16(acc[mf][1], ahi[mf], bh1, bh3);
                    MMA_BF16(acc[mf][0], ahi[mf], bl0, bl2);
                    MMA_BF16(acc[mf][1], ahi[mf], bl1, bl3);
                    MMA_BF16(acc[mf][0], alo[mf], bh0, bh2);
                    MMA_BF16(acc[mf][1], alo[mf], bh1, bh3);
                }
            }

            // ---- dump gate partials to SMEM: gb[kh][row][col], col = ns*16 + ...
            {
                const int rrow = lane >> 2;
                const int cq   = (lane & 3) * 2;
                float* gbh = gb + kh * (32 * 64);
#pragma unroll
                for (int mf = 0; mf < 2; mf++) {
#pragma unroll
                    for (int nf = 0; nf < 2; nf++) {
                        int col = ns * 16 + nf * 8 + cq;
                        float2 v0 = { acc[mf][nf][0], acc[mf][nf][1] };
                        float2 v1 = { acc[mf][nf][2], acc[mf][nf][3] };
                        *(float2*)(gbh + (mf * 16 + rrow) * 64 + col)     = v0;
                        *(float2*)(gbh + (mf * 16 + rrow + 8) * 64 + col) = v1;
                    }
                }
            }
            __syncthreads();
        }

        // ---- elementwise update: thread owns (b, j..j+1), all 4 gates
        float xg[4][2] = { {xv0.x, xv0.y}, {xv0.z, xv0.w},
                           {xv1.x, xv1.y}, {xv1.z, xv1.w} };
        float2 gate[4];
#pragma unroll
        for (int g = 0; g < 4; g++) {
            float gx = 0.0f, gy = 0.0f;
            if (t > 0) {
                int col = g * 16 + 2 * jg;
                float2 p0 = *(float2*)(gb + bl * 64 + col);
                float2 p1 = *(float2*)(gb + 32 * 64 + bl * 64 + col);
                gx = p0.x + p1.x;
                gy = p0.y + p1.y;
            }
            gate[g].x = gx + xg[g][0];
            gate[g].y = gy + xg[g][1];
        }
        float i0 = sigmoidf_(gate[0].x), i1 = sigmoidf_(gate[0].y);
        float f0 = sigmoidf_(gate[1].x), f1 = sigmoidf_(gate[1].y);
        float g0 = tanhf_   (gate[2].x), g1 = tanhf_   (gate[2].y);
        float o0 = sigmoidf_(gate[3].x), o1 = sigmoidf_(gate[3].y);
        c0 = f0 * c0 + i0 * g0;
        c1 = f1 * c1 + i1 * g1;
        float2 hv2;
        hv2.x = o0 * tanhf_(c0);
        hv2.y = o1 * tanhf_(c1);
        __stcg((float2*)(hnext + (size_t)b * HH + j), hv2);
        if (write_hs)
            *(float2*)(g_hs + ((size_t)b * TT + t) * HH + j) = hv2;

        // ---- per-batch-group barrier (16 CTAs; cumulative counters, tight spin)
        __syncthreads();
        if (tid == 0) {
            __threadfence();
            unsigned* arr = &g_arrive2[blockIdx.x * 32];
            volatile unsigned* rel = &g_release2[blockIdx.x * 32];
            unsigned cnt    = atomicAdd(arr, 1u) + 1u;
            unsigned target = ((cnt + 15u) >> 4) << 4;
            if (cnt == target) {
                *rel = cnt;
            } else {
                while ((int)(*rel - target) < 0) { }
            }
            __threadfence();
        }
        __syncthreads();
    }
}

// ---------------- final classifier ----------------
__global__ __launch_bounds__(256) void fc_kernel(
    const float* __restrict__ fcW, const float* __restrict__ fcb,
    float* __restrict__ out)
{
    __shared__ float hrow[HH];
    const int b = blockIdx.x;
    const float* __restrict__ h = g_h[0];
    for (int k = threadIdx.x; k < HH; k += 256) hrow[k] = h[b * HH + k];
    __syncthreads();

    for (int c = threadIdx.x; c < CDIM; c += 256) {
        const float* __restrict__ w = fcW + (size_t)c * HH;
        float s = fcb[c];
#pragma unroll
        for (int k = 0; k < HH; k += 4) {
            float4 wv = *(const float4*)(w + k);
            s += hrow[k + 0] * wv.x;
            s += hrow[k + 1] * wv.y;
            s += hrow[k + 2] * wv.z;
            s += hrow[k + 3] * wv.w;
        }
        out[(size_t)b * CDIM + c] = s;
    }
}

// ---------------- launch ----------------
extern "C" void kernel_launch(void* const* d_in, const int* in_sizes, int n_in,
                              void* d_out, int out_size)
{
    const float* x    = (const float*)d_in[0];
    const float* Wih0 = (const float*)d_in[1];
    const float* Whh0 = (const float*)d_in[2];
    const float* bih0 = (const float*)d_in[3];
    const float* bhh0 = (const float*)d_in[4];
    const float* Wih1 = (const float*)d_in[5];
    const float* Whh1 = (const float*)d_in[6];
    const float* bih1 = (const float*)d_in[7];
    const float* bhh1 = (const float*)d_in[8];
    const float* fcW  = (const float*)d_in[9];
    const float* fcb  = (const float*)d_in[10];
    float* out = (float*)d_out;

    cudaFuncSetAttribute(lstm_persist_kernel,
                         cudaFuncAttributeMaxDynamicSharedMemorySize,
                         PERSIST_SMEM_BYTES);
    cudaFuncSetAttribute(proj_mma_kernel,
                         cudaFuncAttributeMaxDynamicSharedMemorySize,
                         PROJ_SMEM_TOTAL);

    const dim3 proj_grid(G4 / 128, (BB * TT) / 128);  // (8, 1024)
    const dim3 pers_grid(BB / 32, HH / 16);           // (8, 16) = 128 CTAs

    // ---- layer 0 ----
    {
        size_t n4x = (size_t)BB * TT * IDIM / 4;
        size_t n4w = (size_t)G4 * IDIM / 4;
        split_bf16_kernel<<<(unsigned)((n4x + 255) / 256), 256>>>(x, 0, 0, n4x);
        split_bf16_kernel<<<(unsigned)((n4w + 255) / 256), 256>>>(Wih0, 0, 1, n4w);
        proj_mma_kernel<<<proj_grid, 256, PROJ_SMEM_TOTAL>>>(bih0, bhh0, IDIM);
        lstm_persist_kernel<<<pers_grid, 256, PERSIST_SMEM_BYTES>>>(Whh0, 1);
    }

    // ---- layer 1 ----
    {
        size_t n4h = (size_t)BB * TT * HH / 4;
        size_t n4w = (size_t)G4 * HH / 4;
        split_bf16_kernel<<<(unsigned)((n4h + 255) / 256), 256>>>(nullptr, 1, 0, n4h);
        split_bf16_kernel<<<(unsigned)((n4w + 255) / 256), 256>>>(Wih1, 0, 1, n4w);
        proj_mma_kernel<<<proj_grid, 256, PROJ_SMEM_TOTAL>>>(bih1, bhh1, HH);
        lstm_persist_kernel<<<pers_grid, 256, PERSIST_SMEM_BYTES>>>(Whh1, 0);
    }

    // ---- classifier ----
    fc_kernel<<<BB, 256>>>(fcW, fcb, out);
}